// round 16
// speedup vs baseline: 6.6828x; 1.0007x over previous
#include <cuda_runtime.h>
#include <cuda_bf16.h>
#include <cuda_fp16.h>
#include <math.h>
#include <stdint.h>

// Problem constants
#define B_  2
#define L_  1024
#define DM  1024
#define DI  2048
#define NS  16
#define RR  64
#define KC  4
#define MTOT (B_ * L_)      // 2048
#define EPS 1e-5f

#define DBLC (RR + 2 * NS)  // 96
#define SPLITK 8
#define KCHUNK (DI / SPLITK)  // 256
#define WOSPLIT 4

#define NCH 8               // scan chunks
#define CH  (L_ / NCH)      // 128 steps per chunk

#define BIGSPLIT 0x40000000

// ---------------------------------------------------------------------------
// Scratch buffers (device globals; no allocation allowed)
// ---------------------------------------------------------------------------
__device__ __half g_hA[MTOT * DM];
__device__ __half g_hB[MTOT * DM];
__device__ __half g_hWi[(2 * DI) * DM];
__device__ __half g_hWo[DM * DI];
__device__ __half g_hWx[DBLC * DI];
__device__ __half g_hWx_b[DBLC * DI];
__device__ __half g_hWdt[DI * RR];
__device__ __half g_hWdt_b[DI * RR];
__device__ __half g_hx_f[MTOT * DI];        // fp16 x (conv input)
__device__ __half g_hx_b[MTOT * DI];
__device__ __half g_hz[MTOT * DI];          // fp16 z (gate input)
__device__ __half g_hu_f[MTOT * DI];        // fp16 u (GEMM + scan operand)
__device__ __half g_hu_b[MTOT * DI];
__device__ __half g_hdbl_f[MTOT * DBLC];
__device__ __half g_hdbl_b[MTOT * DBLC];
__device__ __half g_hdelta_f[MTOT * DI];    // fp16 delta (scan operand)
__device__ __half g_hdelta_b[MTOT * DI];
__device__ __half g_hy_f[MTOT * DI];        // fp16 y
__device__ __half g_hy_b[MTOT * DI];        // fp16 y (stored pre-flipped)
__device__ __half g_hg[MTOT * DI];

__device__ float g_dblp[2 * SPLITK * MTOT * DBLC];
__device__ float g_dbl_f[MTOT * DBLC];
__device__ float g_dbl_b[MTOT * DBLC];
__device__ float g_wop[WOSPLIT * MTOT * DM];

// scan chunking state
__device__ float g_hloc[2 * B_ * NCH * NS * DI];
__device__ float g_psum[2 * B_ * NCH * DI];

// ---------------------------------------------------------------------------
// fp16 tensor-core GEMM, cp.async 3-stage pipeline, DUAL-BRANCH
//   act: 0 = none(f32 C), 1 = softplus(f32 C), 2 = softplus(fp16 C),
//        3 = none(fp16 C)
//   Cx/NX: cols [0,NX) stored fp16 to Cx (ld NX); rest to C (ld Nn-NX).
// ---------------------------------------------------------------------------
#define BM 128
#define BN 128
#define BK 32
#define BKP 40
#define STAGES 3
#define STG_BYTES ((BM + BN) * BKP * 2)
#define SMEM_TOTAL (STAGES * STG_BYTES)

__device__ __forceinline__ uint32_t smem_u32(const void* p) {
    uint32_t a;
    asm("{ .reg .u64 t; cvta.to.shared.u64 t, %1; cvt.u32.u64 %0, t; }"
        : "=r"(a) : "l"(p));
    return a;
}

__device__ __forceinline__ void ldsm4(uint32_t& r0, uint32_t& r1,
                                      uint32_t& r2, uint32_t& r3, uint32_t addr) {
    asm volatile("ldmatrix.sync.aligned.m8n8.x4.shared.b16 {%0,%1,%2,%3}, [%4];"
                 : "=r"(r0), "=r"(r1), "=r"(r2), "=r"(r3) : "r"(addr));
}

__device__ __forceinline__ void mma_f16(float c[4], const uint32_t a[4],
                                        const uint32_t b[2]) {
    asm volatile(
        "mma.sync.aligned.m16n8k16.row.col.f32.f16.f16.f32 "
        "{%0,%1,%2,%3}, {%4,%5,%6,%7}, {%8,%9}, {%0,%1,%2,%3};"
        : "+f"(c[0]), "+f"(c[1]), "+f"(c[2]), "+f"(c[3])
        : "r"(a[0]), "r"(a[1]), "r"(a[2]), "r"(a[3]), "r"(b[0]), "r"(b[1]));
}

__device__ __forceinline__ float softplus_fast(float v) {
    return (v > 20.f) ? v : __logf(1.f + __expf(v));
}

#define CP_ASYNC16(dst, src, sz) \
    asm volatile("cp.async.cg.shared.global [%0], [%1], 16, %2;" \
                 :: "r"(dst), "l"(src), "r"(sz) : "memory")
#define CP_COMMIT() asm volatile("cp.async.commit_group;" ::: "memory")
#define CP_WAIT1()  asm volatile("cp.async.wait_group 1;" ::: "memory")

__global__ __launch_bounds__(256, 2)
void ha_linear2_kernel(
    const __half* __restrict__ A0, int lda0, const __half* __restrict__ W0, int ldw0,
    const float* __restrict__ bias0, float bs0, float* __restrict__ C0,
    __half* __restrict__ Cx0, int NX0,
    int Nn0, int flip0, int act0,
    const __half* __restrict__ A1, int lda1, const __half* __restrict__ W1, int ldw1,
    const float* __restrict__ bias1, float bs1, float* __restrict__ C1,
    __half* __restrict__ Cx1, int NX1,
    int Nn1, int flip1, int act1,
    int M, int Kd, int splitX, int splitZ, int kchunk)
{
    extern __shared__ __align__(16) char dsm[];
    const uint32_t sbase = smem_u32(dsm);

    int bx = blockIdx.x, bz = blockIdx.z, sel = 0;
    if (bx >= splitX) { sel = 1; bx -= splitX; }
    else if (bz >= splitZ) { sel = 1; bz -= splitZ; }

    const __half* __restrict__ A = sel ? A1 : A0;
    const __half* __restrict__ W = sel ? W1 : W0;
    const float* __restrict__ bias = sel ? bias1 : bias0;
    const float biasScale = sel ? bs1 : bs0;
    float* __restrict__ C = sel ? C1 : C0;
    __half* __restrict__ Cx = sel ? Cx1 : Cx0;
    const int NX   = sel ? NX1 : NX0;
    const int lda  = sel ? lda1 : lda0;
    const int ldw  = sel ? ldw1 : ldw0;
    const int Nn   = sel ? Nn1 : Nn0;
    const int flip = sel ? flip1 : flip0;
    const int act  = sel ? act1 : act0;

    const int tid  = threadIdx.x;
    const int lane = tid & 31;
    const int warp = tid >> 5;
    const int g    = lane >> 2;
    const int tg   = lane & 3;
    const int warpM = (warp & 3) * 32;
    const int warpN = (warp >> 2) * 64;
    const int row0 = blockIdx.y * BM;
    const int col0 = bx * BN;

    int kb = 0, klen = Kd;
    if (kchunk > 0) {
        kb   = bz * kchunk;
        klen = kchunk;
        C   += (size_t)bz * M * Nn;
    }
    const int ntiles = klen / BK;

    int arow[2], wrow[2];
    uint32_t wsz[2];
#pragma unroll
    for (int i = 0; i < 2; i++) {
        int idx = tid + 256 * i;
        int r   = idx >> 2;
        int gr  = row0 + r;
        if (flip) { gr = (gr & ~(L_ - 1)) + ((L_ - 1) - (gr & (L_ - 1))); }
        arow[i] = gr;
        int gn = col0 + r;
        wsz[i]  = (gn < Nn) ? 16u : 0u;
        wrow[i] = (gn < Nn) ? gn : 0;
    }
    const int ld_row   = tid >> 2;
    const int ld_chunk = (tid & 3) * 8;

    const int tquad = lane >> 3;
    const int trow  = lane & 7;
    const int a_m = ((tquad & 1) << 3) + trow;
    const int a_k = (tquad >> 1) << 3;
    const int b_n = ((tquad >> 1) << 3) + trow;
    const int b_k = (tquad & 1) << 3;

    float acc[2][8][4];
#pragma unroll
    for (int mi = 0; mi < 2; mi++)
#pragma unroll
        for (int ni = 0; ni < 8; ni++)
#pragma unroll
            for (int q = 0; q < 4; q++) acc[mi][ni][q] = 0.f;

    auto issue = [&](int t, int s) {
        const uint32_t st = sbase + (uint32_t)s * STG_BYTES;
        const int koff = kb + t * BK + ld_chunk;
#pragma unroll
        for (int i = 0; i < 2; i++) {
            int r = ld_row + 64 * i;
            uint32_t da = st + (uint32_t)r * (BKP * 2) + (uint32_t)ld_chunk * 2;
            CP_ASYNC16(da, A + (size_t)arow[i] * lda + koff, 16u);
        }
#pragma unroll
        for (int i = 0; i < 2; i++) {
            int r = ld_row + 64 * i;
            uint32_t db = st + (uint32_t)(BM * BKP * 2)
                        + (uint32_t)r * (BKP * 2) + (uint32_t)ld_chunk * 2;
            CP_ASYNC16(db, W + (size_t)wrow[i] * ldw + koff, wsz[i]);
        }
    };

#pragma unroll
    for (int s = 0; s < STAGES - 1; s++) {
        if (s < ntiles) issue(s, s);
        CP_COMMIT();
    }

    int cur = 0;
    int nxt = STAGES - 1;
    for (int t = 0; t < ntiles; t++) {
        CP_WAIT1();
        __syncthreads();

        const int tn = t + STAGES - 1;
        if (tn < ntiles) issue(tn, nxt);
        CP_COMMIT();

        const uint32_t stA = sbase + (uint32_t)cur * STG_BYTES;
        const uint32_t stB = stA + (uint32_t)(BM * BKP * 2);

#pragma unroll
        for (int kk = 0; kk < 2; kk++) {
            const uint32_t kbyte = (uint32_t)(kk * 16) * 2;
            uint32_t af[2][4], bf[8][2];
#pragma unroll
            for (int mi = 0; mi < 2; mi++) {
                uint32_t addr = stA + (uint32_t)(warpM + mi * 16 + a_m) * (BKP * 2)
                              + kbyte + (uint32_t)a_k * 2;
                ldsm4(af[mi][0], af[mi][1], af[mi][2], af[mi][3], addr);
            }
#pragma unroll
            for (int nj = 0; nj < 4; nj++) {
                uint32_t addr = stB + (uint32_t)(warpN + nj * 16 + b_n) * (BKP * 2)
                              + kbyte + (uint32_t)b_k * 2;
                ldsm4(bf[2 * nj][0], bf[2 * nj][1], bf[2 * nj + 1][0], bf[2 * nj + 1][1], addr);
            }
#pragma unroll
            for (int mi = 0; mi < 2; mi++)
#pragma unroll
                for (int ni = 0; ni < 8; ni++)
                    mma_f16(acc[mi][ni], af[mi], bf[ni]);
        }

        cur = (cur + 1 == STAGES) ? 0 : cur + 1;
        nxt = (nxt + 1 == STAGES) ? 0 : nxt + 1;
    }

    const bool isX = (Cx != nullptr) && (col0 < NX);
    const int  Nz  = Nn - NX;
#pragma unroll
    for (int mi = 0; mi < 2; mi++) {
        int r0 = row0 + warpM + mi * 16 + g;
#pragma unroll
        for (int ni = 0; ni < 8; ni++) {
            int cb = col0 + warpN + ni * 8 + 2 * tg;
            if (cb < Nn) {
                float v00 = acc[mi][ni][0], v01 = acc[mi][ni][1];
                float v10 = acc[mi][ni][2], v11 = acc[mi][ni][3];
                if (bias) {
                    float b0 = biasScale * bias[cb];
                    float b1 = biasScale * bias[cb + 1];
                    v00 += b0; v01 += b1; v10 += b0; v11 += b1;
                }
                if (act == 1 || act == 2) {
                    v00 = softplus_fast(v00);
                    v01 = softplus_fast(v01);
                    v10 = softplus_fast(v10);
                    v11 = softplus_fast(v11);
                }
                if (isX) {
                    *(__half2*)(Cx + (size_t)r0 * NX + cb)       = __floats2half2_rn(v00, v01);
                    *(__half2*)(Cx + (size_t)(r0 + 8) * NX + cb) = __floats2half2_rn(v10, v11);
                } else if (act == 2) {
                    __half* Ch = (__half*)C;
                    *(__half2*)(Ch + (size_t)r0 * Nn + cb)       = __floats2half2_rn(v00, v01);
                    *(__half2*)(Ch + (size_t)(r0 + 8) * Nn + cb) = __floats2half2_rn(v10, v11);
                } else if (act == 3) {
                    __half* Ch = (__half*)C;
                    int cz = cb - NX;
                    *(__half2*)(Ch + (size_t)r0 * Nz + cz)       = __floats2half2_rn(v00, v01);
                    *(__half2*)(Ch + (size_t)(r0 + 8) * Nz + cz) = __floats2half2_rn(v10, v11);
                } else {
                    int cz = cb - NX;
                    *(float2*)(C + (size_t)r0 * Nz + cz)       = make_float2(v00, v01);
                    *(float2*)(C + (size_t)(r0 + 8) * Nz + cz) = make_float2(v10, v11);
                }
            }
        }
    }
}

// ---------------------------------------------------------------------------
// f32 -> f16 conversion, eight arrays per launch; 32 elems/thread (MLP 8)
// ---------------------------------------------------------------------------
__global__ void cvt8_half_kernel(
    const float* __restrict__ s0, __half* __restrict__ d0, int n0,
    const float* __restrict__ s1, __half* __restrict__ d1, int n1,
    const float* __restrict__ s2, __half* __restrict__ d2, int n2,
    const float* __restrict__ s3, __half* __restrict__ d3, int n3,
    const float* __restrict__ s4, __half* __restrict__ d4, int n4,
    const float* __restrict__ s5, __half* __restrict__ d5, int n5,
    const float* __restrict__ s6, __half* __restrict__ d6, int n6,
    const float* __restrict__ s7, __half* __restrict__ d7, int n7)
{
    int i = (blockIdx.x * blockDim.x + threadIdx.x) * 32;
    const float* s;
    __half* d;
    if (i < n0) { s = s0 + i; d = d0 + i; }
    else if ((i -= n0) < n1) { s = s1 + i; d = d1 + i; }
    else if ((i -= n1) < n2) { s = s2 + i; d = d2 + i; }
    else if ((i -= n2) < n3) { s = s3 + i; d = d3 + i; }
    else if ((i -= n3) < n4) { s = s4 + i; d = d4 + i; }
    else if ((i -= n4) < n5) { s = s5 + i; d = d5 + i; }
    else if ((i -= n5) < n6) { s = s6 + i; d = d6 + i; }
    else if ((i -= n6) < n7) { s = s7 + i; d = d7 + i; }
    else return;

    float4 v[8];
#pragma unroll
    for (int q = 0; q < 8; q++) v[q] = *(const float4*)(s + 4 * q);

#pragma unroll
    for (int q = 0; q < 2; q++) {
        __half2 h0 = __floats2half2_rn(v[4*q+0].x, v[4*q+0].y);
        __half2 h1 = __floats2half2_rn(v[4*q+0].z, v[4*q+0].w);
        __half2 h2 = __floats2half2_rn(v[4*q+1].x, v[4*q+1].y);
        __half2 h3 = __floats2half2_rn(v[4*q+1].z, v[4*q+1].w);
        __half2 h4 = __floats2half2_rn(v[4*q+2].x, v[4*q+2].y);
        __half2 h5 = __floats2half2_rn(v[4*q+2].z, v[4*q+2].w);
        __half2 h6 = __floats2half2_rn(v[4*q+3].x, v[4*q+3].y);
        __half2 h7 = __floats2half2_rn(v[4*q+3].z, v[4*q+3].w);
        *(uint4*)(d + 16 * q)     = make_uint4(*(uint32_t*)&h0, *(uint32_t*)&h1,
                                               *(uint32_t*)&h2, *(uint32_t*)&h3);
        *(uint4*)(d + 16 * q + 8) = make_uint4(*(uint32_t*)&h4, *(uint32_t*)&h5,
                                               *(uint32_t*)&h6, *(uint32_t*)&h7);
    }
}

// ---------------------------------------------------------------------------
// Reduce split-K partials (dbl): f32 + fp16 out
// ---------------------------------------------------------------------------
__global__ void reduce_dbl_kernel(const float* __restrict__ part,
                                  float* __restrict__ of, float* __restrict__ ob,
                                  __half* __restrict__ hf, __half* __restrict__ hb)
{
    const int NV = MTOT * DBLC / 4;
    int i = blockIdx.x * blockDim.x + threadIdx.x;
    if (i >= 2 * NV) return;
    int br = (i >= NV);
    int j  = i - br * NV;
    const float4* p = (const float4*)part + (size_t)br * SPLITK * NV + j;
    float4 s = make_float4(0.f, 0.f, 0.f, 0.f);
#pragma unroll
    for (int k = 0; k < SPLITK; k++) {
        float4 v = p[(size_t)k * NV];
        s.x += v.x; s.y += v.y; s.z += v.z; s.w += v.w;
    }
    ((float4*)(br ? ob : of))[j] = s;
    __half2 h0 = __floats2half2_rn(s.x, s.y);
    __half2 h1 = __floats2half2_rn(s.z, s.w);
    ((uint2*)(br ? hb : hf))[j] = make_uint2(*(uint32_t*)&h0, *(uint32_t*)&h1);
}

// ---------------------------------------------------------------------------
// Reduce Wo split-K partials into out (WOSPLIT partials)
// ---------------------------------------------------------------------------
__global__ void reduce_out_kernel(const float* __restrict__ part,
                                  float* __restrict__ out)
{
    const int NV = MTOT * DM / 4;
    int i = blockIdx.x * blockDim.x + threadIdx.x;
    if (i >= NV) return;
    float4 s = make_float4(0.f, 0.f, 0.f, 0.f);
#pragma unroll
    for (int k = 0; k < WOSPLIT; k++) {
        float4 v = ((const float4*)part)[i + (size_t)k * NV];
        s.x += v.x; s.y += v.y; s.z += v.z; s.w += v.w;
    }
    ((float4*)out)[i] = s;
}

// ---------------------------------------------------------------------------
// Depthwise causal conv1d (K=4) + bias + SiLU; 8 l x 2 d per thread; half2 I/O
// ---------------------------------------------------------------------------
#define CLG 8
__global__ void conv_silu_kernel(const __half* __restrict__ x0,
                                 const float* __restrict__ w0,
                                 const float* __restrict__ b0,
                                 __half* __restrict__ h0,
                                 const __half* __restrict__ x1,
                                 const float* __restrict__ w1,
                                 const float* __restrict__ b1,
                                 __half* __restrict__ h1)
{
    const int br = blockIdx.z;
    const __half* __restrict__ x = br ? x1 : x0;
    const float* __restrict__ w = br ? w1 : w0;
    const float* __restrict__ bi = br ? b1 : b0;
    __half* __restrict__ hu = br ? h1 : h0;

    int idx = blockIdx.x * blockDim.x + threadIdx.x;
    if (idx >= (MTOT / CLG) * (DI / 2)) return;
    const int d    = (idx % (DI / 2)) * 2;
    const int grp  = idx / (DI / 2);
    const int row0 = grp * CLG;
    const int l0   = row0 & (L_ - 1);
    const int bb0  = row0 - l0;

    float2 xv[CLG + KC - 1];
#pragma unroll
    for (int j = 0; j < CLG + KC - 1; j++) {
        int l = l0 - (KC - 1) + j;
        if (l >= 0) {
            __half2 hv = *(const __half2*)(x + (size_t)(bb0 + l) * DI + d);
            xv[j] = __half22float2(hv);
        } else {
            xv[j] = make_float2(0.f, 0.f);
        }
    }
    const float w00 = w[d * KC + 0], w01 = w[d * KC + 1],
                w02 = w[d * KC + 2], w03 = w[d * KC + 3];
    const float w10 = w[(d + 1) * KC + 0], w11 = w[(d + 1) * KC + 1],
                w12 = w[(d + 1) * KC + 2], w13 = w[(d + 1) * KC + 3];
    const float bv0 = bi[d], bv1 = bi[d + 1];

#pragma unroll
    for (int j = 0; j < CLG; j++) {
        float a0 = bv0, a1 = bv1;
        a0 = fmaf(xv[j].x,     w00, a0);  a1 = fmaf(xv[j].y,     w10, a1);
        a0 = fmaf(xv[j + 1].x, w01, a0);  a1 = fmaf(xv[j + 1].y, w11, a1);
        a0 = fmaf(xv[j + 2].x, w02, a0);  a1 = fmaf(xv[j + 2].y, w12, a1);
        a0 = fmaf(xv[j + 3].x, w03, a0);  a1 = fmaf(xv[j + 3].y, w13, a1);
        float s0 = 1.f / (1.f + __expf(-a0));
        float s1 = 1.f / (1.f + __expf(-a1));
        *(__half2*)(hu + (size_t)(row0 + j) * DI + d) =
            __floats2half2_rn(a0 * s0, a1 * s1);
    }
}

// ---------------------------------------------------------------------------
// Chunked selective scan (phase1 / phase2 with inline carry)
//   phase1: chunks 0..NCH-2 only; phase2 backward stores y pre-flipped.
// ---------------------------------------------------------------------------
#define SCAN_TPB 128
#define SCAN_ST  16

__global__ __launch_bounds__(SCAN_TPB)
void scan_phase1(const __half* __restrict__ del_f, const float* __restrict__ dbl_f,
                 const __half* __restrict__ u_f,
                 const __half* __restrict__ del_b, const float* __restrict__ dbl_b,
                 const __half* __restrict__ u_b,
                 const float* __restrict__ Alog_f, const float* __restrict__ Alog_b,
                 float* __restrict__ hloc, float* __restrict__ psum)
{
    const int br = blockIdx.y;
    const __half* __restrict__ del = br ? del_b : del_f;
    const float* __restrict__ dbl  = br ? dbl_b : dbl_f;
    const __half* __restrict__ u   = br ? u_b   : u_f;
    const float* __restrict__ Alog = br ? Alog_b : Alog_f;

    const int tid   = threadIdx.x;
    const int ch    = blockIdx.x % (NCH - 1);
    const int bb    = (blockIdx.x / (NCH - 1)) & 1;
    const int dpart = blockIdx.x / (2 * (NCH - 1));
    const int d     = dpart * SCAN_TPB + tid;
    const int rowb  = bb * L_ + ch * CH;

    bool fast = true;
#pragma unroll
    for (int n = 0; n < NS; n++) {
        float an = expf(Alog[(size_t)d * NS + n]);
        fast = fast && (fabsf(an - (float)(n + 1)) < 1e-4f * (float)(n + 1));
    }

    float h[NS];
#pragma unroll
    for (int n = 0; n < NS; n++) h[n] = 0.f;
    float ps = 0.f;

    __shared__ float4 s_bc[SCAN_ST][4];   // B only

    for (int c0 = 0; c0 < CH; c0 += SCAN_ST) {
        float rdel[SCAN_ST], ru[SCAN_ST];
#pragma unroll
        for (int k = 0; k < SCAN_ST; k++) {
            size_t off = (size_t)(rowb + c0 + k) * DI + d;
            rdel[k] = __half2float(del[off]);
            ru[k]   = __half2float(u[off]);
        }
        __syncthreads();
        if (tid < 64) {
            int k = tid >> 2;
            int q = tid & 3;
            size_t off = (size_t)(rowb + c0 + k) * DBLC + RR + q * 4;
            s_bc[k][q] = *(const float4*)(dbl + off);
        }
        __syncthreads();

        if (fast) {
#pragma unroll
            for (int k = 0; k < SCAN_ST; k++) {
                float dl = rdel[k];
                float du = dl * ru[k];
                ps += dl;
                float e = __expf(-dl);
                float4 V0 = s_bc[k][0], V1 = s_bc[k][1], V2 = s_bc[k][2], V3 = s_bc[k][3];
                float Bv[NS] = {V0.x,V0.y,V0.z,V0.w, V1.x,V1.y,V1.z,V1.w,
                                V2.x,V2.y,V2.z,V2.w, V3.x,V3.y,V3.z,V3.w};
                float p = e;
#pragma unroll
                for (int n = 0; n < NS; n++) {
                    h[n] = fmaf(p, h[n], du * Bv[n]);
                    p   *= e;
                }
            }
        } else {
#pragma unroll
            for (int k = 0; k < SCAN_ST; k++) {
                float dl = rdel[k];
                float du = dl * ru[k];
                ps += dl;
                const float* bc = (const float*)s_bc[k];
#pragma unroll
                for (int n = 0; n < NS; n++) {
                    float an = expf(Alog[(size_t)d * NS + n]);
                    float dA = __expf(-dl * an);
                    h[n] = fmaf(dA, h[n], du * bc[n]);
                }
            }
        }
    }

    const int cbase = ((br * B_ + bb) * NCH + ch);
    psum[(size_t)cbase * DI + d] = ps;
#pragma unroll
    for (int n = 0; n < NS; n++)
        hloc[((size_t)cbase * NS + n) * DI + d] = h[n];
}

__global__ __launch_bounds__(SCAN_TPB)
void scan_phase2(const __half* __restrict__ del_f, const float* __restrict__ dbl_f,
                 const __half* __restrict__ u_f,
                 const __half* __restrict__ del_b, const float* __restrict__ dbl_b,
                 const __half* __restrict__ u_b,
                 const float* __restrict__ Alog_f, const float* __restrict__ D_f,
                 const float* __restrict__ Alog_b, const float* __restrict__ D_b,
                 const float* __restrict__ hloc, const float* __restrict__ psum,
                 __half* __restrict__ y_f, __half* __restrict__ y_b)
{
    const int br = blockIdx.y;
    const __half* __restrict__ del = br ? del_b : del_f;
    const float* __restrict__ dbl  = br ? dbl_b : dbl_f;
    const __half* __restrict__ u   = br ? u_b   : u_f;
    const float* __restrict__ Alog = br ? Alog_b : Alog_f;
    const float* __restrict__ Dv_p = br ? D_b : D_f;
    __half* __restrict__ yout      = br ? y_b : y_f;

    const int tid   = threadIdx.x;
    const int ch    = blockIdx.x & (NCH - 1);
    const int bb    = (blockIdx.x >> 3) & 1;
    const int dpart = blockIdx.x >> 4;
    const int d     = dpart * SCAN_TPB + tid;
    const int rowb  = bb * L_ + ch * CH;

    bool fast = true;
#pragma unroll
    for (int n = 0; n < NS; n++) {
        float an = expf(Alog[(size_t)d * NS + n]);
        fast = fast && (fabsf(an - (float)(n + 1)) < 1e-4f * (float)(n + 1));
    }
    const float Dv = Dv_p[d];

    float h[NS];
#pragma unroll
    for (int n = 0; n < NS; n++) h[n] = 0.f;
    for (int c = 0; c < ch; c++) {
        const size_t cb = ((size_t)(br * B_ + bb) * NCH + c);
        float ps = psum[cb * DI + d];
        if (fast) {
            float E = __expf(-ps);
            float p = E;
#pragma unroll
            for (int n = 0; n < NS; n++) {
                h[n] = fmaf(p, h[n], hloc[(cb * NS + n) * DI + d]);
                p   *= E;
            }
        } else {
#pragma unroll
            for (int n = 0; n < NS; n++) {
                float an = expf(Alog[(size_t)d * NS + n]);
                float P = __expf(-ps * an);
                h[n] = fmaf(P, h[n], hloc[(cb * NS + n) * DI + d]);
            }
        }
    }

    __shared__ float4 s_bc[SCAN_ST][8];

    for (int c0 = 0; c0 < CH; c0 += SCAN_ST) {
        float rdel[SCAN_ST], ru[SCAN_ST];
#pragma unroll
        for (int k = 0; k < SCAN_ST; k++) {
            size_t off = (size_t)(rowb + c0 + k) * DI + d;
            rdel[k] = __half2float(del[off]);
            ru[k]   = __half2float(u[off]);
        }
        __syncthreads();
        {
            int k = tid >> 3;
            int q = tid & 7;
            size_t off = (size_t)(rowb + c0 + k) * DBLC + RR + q * 4;
            s_bc[k][q] = *(const float4*)(dbl + off);
        }
        __syncthreads();

        if (fast) {
#pragma unroll
            for (int k = 0; k < SCAN_ST; k++) {
                float dl = rdel[k];
                float uu = ru[k];
                float du = dl * uu;
                float e  = __expf(-dl);
                float4 V0 = s_bc[k][0], V1 = s_bc[k][1], V2 = s_bc[k][2], V3 = s_bc[k][3];
                float4 W0 = s_bc[k][4], W1 = s_bc[k][5], W2 = s_bc[k][6], W3 = s_bc[k][7];
                float Bv[NS] = {V0.x,V0.y,V0.z,V0.w, V1.x,V1.y,V1.z,V1.w,
                                V2.x,V2.y,V2.z,V2.w, V3.x,V3.y,V3.z,V3.w};
                float Cv[NS] = {W0.x,W0.y,W0.z,W0.w, W1.x,W1.y,W1.z,W1.w,
                                W2.x,W2.y,W2.z,W2.w, W3.x,W3.y,W3.z,W3.w};
                float p  = e;
                float yv0 = 0.f, yv1 = 0.f;
#pragma unroll
                for (int n = 0; n < NS; n++) {
                    h[n] = fmaf(p, h[n], du * Bv[n]);
                    if (n & 1) yv1 = fmaf(h[n], Cv[n], yv1);
                    else       yv0 = fmaf(h[n], Cv[n], yv0);
                    p   *= e;
                }
                float yv = fmaf(uu, Dv, yv0 + yv1);
                int lrow = ch * CH + c0 + k;
                int srow = bb * L_ + (br ? (L_ - 1 - lrow) : lrow);
                yout[(size_t)srow * DI + d] = __float2half_rn(yv);
            }
        } else {
#pragma unroll
            for (int k = 0; k < SCAN_ST; k++) {
                float dl = rdel[k];
                float uu = ru[k];
                float du = dl * uu;
                float yv = 0.f;
                const float* bc = (const float*)s_bc[k];
#pragma unroll
                for (int n = 0; n < NS; n++) {
                    float an = expf(Alog[(size_t)d * NS + n]);
                    float dA = __expf(-dl * an);
                    h[n] = fmaf(dA, h[n], du * bc[n]);
                    yv   = fmaf(h[n], bc[NS + n], yv);
                }
                yv = fmaf(uu, Dv, yv);
                int lrow = ch * CH + c0 + k;
                int srow = bb * L_ + (br ? (L_ - 1 - lrow) : lrow);
                yout[(size_t)srow * DI + d] = __float2half_rn(yv);
            }
        }
    }
}

// ---------------------------------------------------------------------------
// Gate (y * silu(z)) + RMSNorm * norm_w; y_b already flipped
// ---------------------------------------------------------------------------
__global__ __launch_bounds__(256)
void gate_rms_kernel(const __half* __restrict__ yf, const __half* __restrict__ yb,
                     const __half* __restrict__ z, const float* __restrict__ nw,
                     __half* __restrict__ g)
{
    const int row = blockIdx.x;
    const int tid = threadIdx.x;

    __shared__ float sg[DI];
    __shared__ float red[8];

    float ss = 0.f;
#pragma unroll
    for (int it = 0; it < DI / 512; it++) {
        int d = (tid + it * 256) * 2;
        float2 y0 = __half22float2(*(const __half2*)(yf + (size_t)row * DI + d));
        float2 y1 = __half22float2(*(const __half2*)(yb + (size_t)row * DI + d));
        float2 zz = __half22float2(*(const __half2*)(z + (size_t)row * DI + d));
        float sz0 = zz.x / (1.f + __expf(-zz.x));
        float sz1 = zz.y / (1.f + __expf(-zz.y));
        float g0 = (y0.x + y1.x) * sz0;
        float g1 = (y0.y + y1.y) * sz1;
        *(float2*)&sg[d] = make_float2(g0, g1);
        ss = fmaf(g0, g0, ss);
        ss = fmaf(g1, g1, ss);
    }
#pragma unroll
    for (int o = 16; o; o >>= 1) ss += __shfl_xor_sync(0xFFFFFFFFu, ss, o);
    if ((tid & 31) == 0) red[tid >> 5] = ss;
    __syncthreads();
    float total = red[0] + red[1] + red[2] + red[3] + red[4] + red[5] + red[6] + red[7];
    float scale = rsqrtf(total / (float)DI + EPS);

#pragma unroll
    for (int it = 0; it < DI / 512; it++) {
        int d = (tid + it * 256) * 2;
        float2 gv = *(const float2*)&sg[d];
        float2 nv = *(const float2*)(nw + d);
        *(__half2*)(g + (size_t)row * DI + d) =
            __floats2half2_rn(gv.x * scale * nv.x, gv.y * scale * nv.y);
    }
}

// ---------------------------------------------------------------------------
// Launch
// ---------------------------------------------------------------------------
extern "C" void kernel_launch(void* const* d_in, const int* in_sizes, int n_in,
                              void* d_out, int out_size)
{
    (void)in_sizes; (void)n_in; (void)out_size;
    const float* a       = (const float*)d_in[0];
    const float* b       = (const float*)d_in[1];
    const float* Wi      = (const float*)d_in[2];
    const float* conv_w  = (const float*)d_in[3];
    const float* conv_b  = (const float*)d_in[4];
    const float* Wx      = (const float*)d_in[5];
    const float* Wdt     = (const float*)d_in[6];
    const float* bdt     = (const float*)d_in[7];
    const float* A_log   = (const float*)d_in[8];
    const float* D       = (const float*)d_in[9];
    const float* conv_w_b = (const float*)d_in[10];
    const float* conv_b_b = (const float*)d_in[11];
    const float* Wx_b    = (const float*)d_in[12];
    const float* Wdt_b   = (const float*)d_in[13];
    const float* bdt_b   = (const float*)d_in[14];
    const float* A_log_b = (const float*)d_in[15];
    const float* D_b     = (const float*)d_in[16];
    const float* Wo      = (const float*)d_in[17];
    const float* norm_w  = (const float*)d_in[18];
    float* out = (float*)d_out;

    __half *p_hA, *p_hB, *p_hWi, *p_hWo, *p_hWx, *p_hWx_b, *p_hWdt, *p_hWdt_b;
    __half *p_hx_f, *p_hx_b, *p_hz, *p_hu_f, *p_hu_b, *p_hdbl_f, *p_hdbl_b;
    __half *p_hdelta_f, *p_hdelta_b, *p_hy_f, *p_hy_b, *p_hg;
    float *p_dblp, *p_dbl_f, *p_dbl_b, *p_wop;
    float *p_hloc, *p_psum;
    cudaGetSymbolAddress((void**)&p_hA, g_hA);
    cudaGetSymbolAddress((void**)&p_hB, g_hB);
    cudaGetSymbolAddress((void**)&p_hWi, g_hWi);
    cudaGetSymbolAddress((void**)&p_hWo, g_hWo);
    cudaGetSymbolAddress((void**)&p_hWx, g_hWx);
    cudaGetSymbolAddress((void**)&p_hWx_b, g_hWx_b);
    cudaGetSymbolAddress((void**)&p_hWdt, g_hWdt);
    cudaGetSymbolAddress((void**)&p_hWdt_b, g_hWdt_b);
    cudaGetSymbolAddress((void**)&p_hx_f, g_hx_f);
    cudaGetSymbolAddress((void**)&p_hx_b, g_hx_b);
    cudaGetSymbolAddress((void**)&p_hz, g_hz);
    cudaGetSymbolAddress((void**)&p_hu_f, g_hu_f);
    cudaGetSymbolAddress((void**)&p_hu_b, g_hu_b);
    cudaGetSymbolAddress((void**)&p_hdbl_f, g_hdbl_f);
    cudaGetSymbolAddress((void**)&p_hdbl_b, g_hdbl_b);
    cudaGetSymbolAddress((void**)&p_hdelta_f, g_hdelta_f);
    cudaGetSymbolAddress((void**)&p_hdelta_b, g_hdelta_b);
    cudaGetSymbolAddress((void**)&p_hy_f, g_hy_f);
    cudaGetSymbolAddress((void**)&p_hy_b, g_hy_b);
    cudaGetSymbolAddress((void**)&p_hg, g_hg);
    cudaGetSymbolAddress((void**)&p_dblp, g_dblp);
    cudaGetSymbolAddress((void**)&p_dbl_f, g_dbl_f);
    cudaGetSymbolAddress((void**)&p_dbl_b, g_dbl_b);
    cudaGetSymbolAddress((void**)&p_wop, g_wop);
    cudaGetSymbolAddress((void**)&p_hloc, g_hloc);
    cudaGetSymbolAddress((void**)&p_psum, g_psum);

    const int TPB = 256;
    cudaFuncSetAttribute(ha_linear2_kernel,
                         cudaFuncAttributeMaxDynamicSharedMemorySize, SMEM_TOTAL);

    // 0. convert inputs/weights to fp16 (one 8-array launch, 32 elems/thread)
    {
        int nA = MTOT * DM, nB = MTOT * DM, nC = 2 * DI * DM, nD = DM * DI;
        int n0 = DBLC * DI, n1 = DBLC * DI, n2 = DI * RR, n3 = DI * RR;
        int ntot = nA + nB + nC + nD + n0 + n1 + n2 + n3;
        cvt8_half_kernel<<<(ntot / 32 + TPB - 1) / TPB, TPB>>>(
            a, p_hA, nA, b, p_hB, nB, Wi, p_hWi, nC, Wo, p_hWo, nD,
            Wx, p_hWx, n0, Wx_b, p_hWx_b, n1, Wdt, p_hWdt, n2, Wdt_b, p_hWdt_b, n3);
    }

    // 1. fused xz GEMM: fwd x->fp16 + z->fp16; bwd x->fp16
    ha_linear2_kernel<<<dim3(32 + 16, MTOT / BM, 1), TPB, SMEM_TOTAL>>>(
        p_hA, DM, p_hWi, DM, nullptr, 0.f, (float*)p_hz, p_hx_f, DI, 2 * DI, 0, 3,
        p_hB, DM, p_hWi, DM, nullptr, 0.f, nullptr, p_hx_b, DI, DI, 1, 0,
        MTOT, DM, /*splitX=*/32, /*splitZ=*/BIGSPLIT, 0);

    // 2. conv + silu (8 l x 2 d per thread, both branches)
    conv_silu_kernel<<<dim3((MTOT / CLG) * (DI / 2) / TPB, 1, 2), TPB>>>(
        p_hx_f, conv_w, conv_b, p_hu_f,
        p_hx_b, conv_w_b, conv_b_b, p_hu_b);

    // 3. fused dbl = u @ Wx^T [2048,96], split-K both branches
    ha_linear2_kernel<<<dim3(1, MTOT / BM, 2 * SPLITK), TPB, SMEM_TOTAL>>>(
        p_hu_f, DI, p_hWx, DI, nullptr, 0.f, p_dblp, nullptr, 0, DBLC, 0, 0,
        p_hu_b, DI, p_hWx_b, DI, nullptr, 0.f, p_dblp + (size_t)SPLITK * MTOT * DBLC,
        nullptr, 0, DBLC, 0, 0,
        MTOT, DI, /*splitX=*/BIGSPLIT, /*splitZ=*/SPLITK, KCHUNK);

    // 4. reduce partials -> dbl (f32 + fp16)
    {
        int nthreads = 2 * MTOT * DBLC / 4;
        reduce_dbl_kernel<<<(nthreads + TPB - 1) / TPB, TPB>>>(
            p_dblp, p_dbl_f, p_dbl_b, p_hdbl_f, p_hdbl_b);
    }

    // 5. fused delta = softplus(dt @ Wdt^T + 2*bdt), fp16 out, both branches
    ha_linear2_kernel<<<dim3(DI / BN, MTOT / BM, 2), TPB, SMEM_TOTAL>>>(
        p_hdbl_f, DBLC, p_hWdt, RR, bdt, 2.f, (float*)p_hdelta_f, nullptr, 0, DI, 0, 2,
        p_hdbl_b, DBLC, p_hWdt_b, RR, bdt_b, 2.f, (float*)p_hdelta_b, nullptr, 0, DI, 0, 2,
        MTOT, RR, /*splitX=*/BIGSPLIT, /*splitZ=*/1, 0);

    // 6. chunked selective scan; phase1 skips last chunk; phase2 flips y_b
    scan_phase1<<<dim3((DI / SCAN_TPB) * B_ * (NCH - 1), 2), SCAN_TPB>>>(
        p_hdelta_f, p_dbl_f, p_hu_f, p_hdelta_b, p_dbl_b, p_hu_b,
        A_log, A_log_b, p_hloc, p_psum);
    scan_phase2<<<dim3((DI / SCAN_TPB) * B_ * NCH, 2), SCAN_TPB>>>(
        p_hdelta_f, p_dbl_f, p_hu_f, p_hdelta_b, p_dbl_b, p_hu_b,
        A_log, D, A_log_b, D_b, p_hloc, p_psum, p_hy_f, p_hy_b);

    // 7. gate + rmsnorm (y_b pre-flipped)
    gate_rms_kernel<<<MTOT, TPB>>>(p_hy_f, p_hy_b, p_hz, norm_w, p_hg);

    // 8. out = g @ Wo^T [2048,1024], split-K x4
    ha_linear2_kernel<<<dim3(DM / BN, MTOT / BM, WOSPLIT), TPB, SMEM_TOTAL>>>(
        p_hg, DI, p_hWo, DI, nullptr, 0.f, p_wop, nullptr, 0, DM, 0, 0,
        p_hg, DI, p_hWo, DI, nullptr, 0.f, p_wop, nullptr, 0, DM, 0, 0,
        MTOT, DI, /*splitX=*/BIGSPLIT, /*splitZ=*/BIGSPLIT, DI / WOSPLIT);
    reduce_out_kernel<<<(MTOT * DM / 4 + TPB - 1) / TPB, TPB>>>(p_wop, out);
}